// round 1
// baseline (speedup 1.0000x reference)
#include <cuda_runtime.h>
#include <cuda_bf16.h>

// PIF integrate-and-fire spike count, elementwise over 51.4M fp32 elements.
// s(x) = sum_{t=0..7} [ (x + 0.5 - t) >= 1 ], computed with the exact same
// repeated fp32 subtraction as the reference to match rounding behavior.
//
// Memory-bound: 8B/elem traffic, ~411 MB total. float4 vectorized, no tail
// (N = 64*256*56*56 is divisible by 4).

#define T_STEPS 8
#define V_INIT 0.5f
#define V_THRESH 1.0f

__device__ __forceinline__ float pif_count(float x) {
    float v = x + V_INIT;
    float s = 0.0f;
#pragma unroll
    for (int t = 0; t < T_STEPS; ++t) {
        s += (v >= V_THRESH) ? 1.0f : 0.0f;
        v -= V_THRESH;
    }
    return s;
}

__global__ void pif_kernel(const float4* __restrict__ x, float4* __restrict__ out, int n4) {
    int i = blockIdx.x * blockDim.x + threadIdx.x;
    if (i >= n4) return;
    float4 v = x[i];
    float4 r;
    r.x = pif_count(v.x);
    r.y = pif_count(v.y);
    r.z = pif_count(v.z);
    r.w = pif_count(v.w);
    out[i] = r;
}

extern "C" void kernel_launch(void* const* d_in, const int* in_sizes, int n_in,
                              void* d_out, int out_size) {
    const float* x = (const float*)d_in[0];
    float* out = (float*)d_out;
    int n = in_sizes[0];          // 51,380,224 — divisible by 4
    int n4 = n >> 2;
    int threads = 256;
    int blocks = (n4 + threads - 1) / threads;
    pif_kernel<<<blocks, threads>>>((const float4*)x, (float4*)out, n4);
}

// round 2
// speedup vs baseline: 1.0970x; 1.0970x over previous
#include <cuda_runtime.h>
#include <cuda_bf16.h>

// PIF integrate-and-fire spike count, elementwise.
// Reference: v0 = x + 0.5; 8x { s += (v>=1); v -= 1 }.
// Since subtracting 1.0f is exact in fp32 for the value range here, the loop
// is bit-identical to: s = clamp(floor(x + 0.5f), 0, 8).
//
// Memory-bound: 8B/elem, ~411 MB. float4 x2 per thread (block-strided, fully
// coalesced), streaming cache hints (single-touch data).

__device__ __forceinline__ float pif_count(float x) {
    return fminf(8.0f, fmaxf(0.0f, floorf(x + 0.5f)));
}

__device__ __forceinline__ float4 pif4(float4 v) {
    float4 r;
    r.x = pif_count(v.x);
    r.y = pif_count(v.y);
    r.z = pif_count(v.z);
    r.w = pif_count(v.w);
    return r;
}

__global__ void pif_kernel(const float4* __restrict__ x, float4* __restrict__ out, int n4) {
    int base = blockIdx.x * (blockDim.x * 2) + threadIdx.x;
    int i0 = base;
    int i1 = base + blockDim.x;
    // Front-batch both loads for MLP
    float4 a, b;
    bool ok0 = i0 < n4;
    bool ok1 = i1 < n4;
    if (ok0) a = __ldcs(&x[i0]);
    if (ok1) b = __ldcs(&x[i1]);
    if (ok0) __stcs(&out[i0], pif4(a));
    if (ok1) __stcs(&out[i1], pif4(b));
}

extern "C" void kernel_launch(void* const* d_in, const int* in_sizes, int n_in,
                              void* d_out, int out_size) {
    const float* x = (const float*)d_in[0];
    float* out = (float*)d_out;
    int n = in_sizes[0];            // 51,380,224 — divisible by 8
    int n4 = n >> 2;                // float4 count
    int threads = 256;
    int per_block = threads * 2;    // two float4 per thread
    int blocks = (n4 + per_block - 1) / per_block;
    pif_kernel<<<blocks, threads>>>((const float4*)x, (float4*)out, n4);
}